// round 3
// baseline (speedup 1.0000x reference)
#include <cuda_runtime.h>
#include <cuda_bf16.h>
#include <cstdint>

#define NPTS  65536
#define DIMS  512
#define KCENT 512

// Device-global scratch (no allocations allowed in kernel_launch)
static __device__ __nv_bfloat16 g_xbf16[(size_t)NPTS * DIMS];   // 64 MB
static __device__ __nv_bfloat16 g_cbf16[KCENT * DIMS];          // 512 KB
static __device__ float        g_xsq1[NPTS];                    // 1 + ||x||^2
static __device__ float        g_csq[KCENT];                    // ||c||^2

__device__ __forceinline__ uint32_t smem_u32(const void* p) {
    uint32_t a;
    asm("{ .reg .u64 t; cvta.to.shared.u64 t, %1; cvt.u32.u64 %0, t; }"
        : "=r"(a) : "l"(p));
    return a;
}

__device__ __forceinline__ void ldsm_x4(uint32_t addr, uint32_t* r) {
    asm volatile("ldmatrix.sync.aligned.m8n8.x4.shared.b16 {%0,%1,%2,%3}, [%4];"
                 : "=r"(r[0]), "=r"(r[1]), "=r"(r[2]), "=r"(r[3]) : "r"(addr));
}

__device__ __forceinline__ void mma16816(float* d, const uint32_t* a,
                                         uint32_t b0, uint32_t b1) {
    asm volatile(
        "mma.sync.aligned.m16n8k16.row.col.f32.bf16.bf16.f32 "
        "{%0,%1,%2,%3}, {%4,%5,%6,%7}, {%8,%9}, {%0,%1,%2,%3};"
        : "+f"(d[0]), "+f"(d[1]), "+f"(d[2]), "+f"(d[3])
        : "r"(a[0]), "r"(a[1]), "r"(a[2]), "r"(a[3]), "r"(b0), "r"(b1));
}

__device__ __forceinline__ float frcp(float v) {
    float r;
    asm("rcp.approx.f32 %0, %1;" : "=f"(r) : "f"(v));
    return r;
}

// ------------------------------------------------------------------
// Prepass: one warp per row; f32 -> bf16 + sum of squares
// ------------------------------------------------------------------
__global__ void __launch_bounds__(256) prep_x(const float* __restrict__ x) {
    const int wid = threadIdx.x >> 5, lane = threadIdx.x & 31;
    const int row = blockIdx.x * 8 + wid;
    const float4* src = reinterpret_cast<const float4*>(x + (size_t)row * DIMS);
    uint2* dst = reinterpret_cast<uint2*>(g_xbf16 + (size_t)row * DIMS);
    float s = 0.0f;
#pragma unroll
    for (int i = 0; i < 4; i++) {
        float4 v = src[lane + i * 32];
        s = fmaf(v.x, v.x, s); s = fmaf(v.y, v.y, s);
        s = fmaf(v.z, v.z, s); s = fmaf(v.w, v.w, s);
        __nv_bfloat162 p0 = __floats2bfloat162_rn(v.x, v.y);
        __nv_bfloat162 p1 = __floats2bfloat162_rn(v.z, v.w);
        uint2 u;
        u.x = *reinterpret_cast<uint32_t*>(&p0);
        u.y = *reinterpret_cast<uint32_t*>(&p1);
        dst[lane + i * 32] = u;
    }
#pragma unroll
    for (int o = 16; o > 0; o >>= 1) s += __shfl_xor_sync(0xFFFFFFFFu, s, o);
    if (lane == 0) g_xsq1[row] = 1.0f + s;
}

__global__ void __launch_bounds__(256) prep_c(const float* __restrict__ c) {
    const int wid = threadIdx.x >> 5, lane = threadIdx.x & 31;
    const int row = blockIdx.x * 8 + wid;
    const float4* src = reinterpret_cast<const float4*>(c + (size_t)row * DIMS);
    uint2* dst = reinterpret_cast<uint2*>(g_cbf16 + (size_t)row * DIMS);
    float s = 0.0f;
#pragma unroll
    for (int i = 0; i < 4; i++) {
        float4 v = src[lane + i * 32];
        s = fmaf(v.x, v.x, s); s = fmaf(v.y, v.y, s);
        s = fmaf(v.z, v.z, s); s = fmaf(v.w, v.w, s);
        __nv_bfloat162 p0 = __floats2bfloat162_rn(v.x, v.y);
        __nv_bfloat162 p1 = __floats2bfloat162_rn(v.z, v.w);
        uint2 u;
        u.x = *reinterpret_cast<uint32_t*>(&p0);
        u.y = *reinterpret_cast<uint32_t*>(&p1);
        dst[lane + i * 32] = u;
    }
#pragma unroll
    for (int o = 16; o > 0; o >>= 1) s += __shfl_xor_sync(0xFFFFFFFFu, s, o);
    if (lane == 0) g_csq[row] = s;
}

// ------------------------------------------------------------------
// Main fused kernel: CTA = 64 rows x 512 centroids, K pipelined
// ------------------------------------------------------------------
// smem layout (bytes): csq[512]f @0, xsq[64]f @2048, rowsum[64]f @2304,
// stages @2560: each stage = A(64 rows x 80B) + B(512 rows x 80B) = 46080
#define SM_CSQ   0
#define SM_XSQ   2048
#define SM_RSUM  2304
#define SM_STAGE 2560
#define STAGE_SZ 46080
#define B_OFF    5120
#define ROWPITCH 80
#define NSTAGE   3
#define SMEM_TOTAL (SM_STAGE + NSTAGE * STAGE_SZ)   // 140800

__device__ __forceinline__ void issue_stage(uint32_t sb, int s, int k0,
                                            int m0, int tid) {
    const uint32_t st = sb + SM_STAGE + s * STAGE_SZ;
    // B: 512 rows x 32 bf16 (64B = 4 x 16B chunks) -> 2048 chunks
#pragma unroll
    for (int i = 0; i < 8; i++) {
        const int idx = tid + i * 256;
        const int n = idx >> 2, c = idx & 3;
        const uint32_t dst = st + B_OFF + n * ROWPITCH + c * 16;
        const __nv_bfloat16* src = g_cbf16 + ((size_t)n * DIMS + k0 + c * 8);
        asm volatile("cp.async.cg.shared.global [%0], [%1], 16;"
                     :: "r"(dst), "l"(src) : "memory");
    }
    // A: 64 rows x 4 chunks = 256 chunks
    {
        const int r = tid >> 2, c = tid & 3;
        const uint32_t dst = st + r * ROWPITCH + c * 16;
        const __nv_bfloat16* src = g_xbf16 + ((size_t)(m0 + r) * DIMS + k0 + c * 8);
        asm volatile("cp.async.cg.shared.global [%0], [%1], 16;"
                     :: "r"(dst), "l"(src) : "memory");
    }
    asm volatile("cp.async.commit_group;" ::: "memory");
}

__global__ void __launch_bounds__(256, 1)
clu_main(float* __restrict__ out) {
    extern __shared__ char smem[];
    const uint32_t sb = smem_u32(smem);
    const int tid = threadIdx.x;
    const int lane = tid & 31;
    const int wid = tid >> 5;
    const int mw = wid & 1;       // 0..1
    const int nw = wid >> 1;      // 0..3
    const int m0 = blockIdx.x * 64;

    float* csq = reinterpret_cast<float*>(smem + SM_CSQ);
    float* xsq = reinterpret_cast<float*>(smem + SM_XSQ);
    float* rsum = reinterpret_cast<float*>(smem + SM_RSUM);

    csq[tid] = g_csq[tid];
    csq[tid + 256] = g_csq[tid + 256];
    if (tid < 64) {
        xsq[tid] = g_xsq1[m0 + tid];
        rsum[tid] = 0.0f;
    }

    // prologue: stages 0..2
    issue_stage(sb, 0, 0, m0, tid);
    issue_stage(sb, 1, 32, m0, tid);
    issue_stage(sb, 2, 64, m0, tid);

    float acc[2][16][4];
#pragma unroll
    for (int mt = 0; mt < 2; mt++)
#pragma unroll
        for (int nt = 0; nt < 16; nt++)
#pragma unroll
            for (int c = 0; c < 4; c++) acc[mt][nt][c] = 0.0f;

    // ldmatrix lane address components
    const int g = lane >> 3;
    const int row_off = (lane & 7) + (g & 1) * 8;
    const int kb = (g >> 1) * 16;

#pragma unroll 1
    for (int it = 0; it < 16; ++it) {
        if (it < 14)      asm volatile("cp.async.wait_group 2;" ::: "memory");
        else if (it == 14) asm volatile("cp.async.wait_group 1;" ::: "memory");
        else               asm volatile("cp.async.wait_group 0;" ::: "memory");
        __syncthreads();

        const uint32_t st = sb + SM_STAGE + (it % 3) * STAGE_SZ;
        const uint32_t a_row = st + (mw * 32 + row_off) * ROWPITCH + kb;
        const uint32_t b_row = st + B_OFF + (nw * 128 + row_off) * ROWPITCH + kb;

#pragma unroll
        for (int ks = 0; ks < 2; ks++) {
            uint32_t a[2][4];
#pragma unroll
            for (int mt = 0; mt < 2; mt++)
                ldsm_x4(a_row + mt * 16 * ROWPITCH + ks * 32, a[mt]);
            uint32_t b[8][4];
#pragma unroll
            for (int p = 0; p < 8; p++)
                ldsm_x4(b_row + p * 16 * ROWPITCH + ks * 32, b[p]);
            // ldmatrix.x4 tiles: r0 = n[0:8)k[0:8), r1 = n[8:16)k[0:8),
            //                    r2 = n[0:8)k[8:16), r3 = n[8:16)k[8:16)
            // mma B fragment = {k-low, k-high} of ONE n-tile:
#pragma unroll
            for (int mt = 0; mt < 2; mt++)
#pragma unroll
                for (int p = 0; p < 8; p++) {
                    mma16816(acc[mt][2 * p],     a[mt], b[p][0], b[p][2]);
                    mma16816(acc[mt][2 * p + 1], a[mt], b[p][1], b[p][3]);
                }
        }
        __syncthreads();
        if (it + 3 < 16) issue_stage(sb, it % 3, (it + 3) * 32, m0, tid);
    }

    // ---- Epilogue: q = rcp(1 + ||x||^2 + ||c||^2 - 2 acc); rowsum; norm ----
    const int rquad = lane >> 2;
    const int cpair = (lane & 3) * 2;

#pragma unroll
    for (int mt = 0; mt < 2; mt++) {
        const float xlo = xsq[mw * 32 + mt * 16 + rquad];
        const float xhi = xsq[mw * 32 + mt * 16 + rquad + 8];
        float slo = 0.0f, shi = 0.0f;
#pragma unroll
        for (int nt = 0; nt < 16; nt++) {
            const int col = nw * 128 + nt * 8 + cpair;
            const float c0 = csq[col], c1 = csq[col + 1];
            float q0 = frcp(fmaf(-2.0f, acc[mt][nt][0], xlo + c0));
            float q1 = frcp(fmaf(-2.0f, acc[mt][nt][1], xlo + c1));
            float q2 = frcp(fmaf(-2.0f, acc[mt][nt][2], xhi + c0));
            float q3 = frcp(fmaf(-2.0f, acc[mt][nt][3], xhi + c1));
            acc[mt][nt][0] = q0; acc[mt][nt][1] = q1;
            acc[mt][nt][2] = q2; acc[mt][nt][3] = q3;
            slo += q0 + q1; shi += q2 + q3;
        }
        // reduce across the 4 lanes of the quad
        slo += __shfl_xor_sync(0xFFFFFFFFu, slo, 1);
        slo += __shfl_xor_sync(0xFFFFFFFFu, slo, 2);
        shi += __shfl_xor_sync(0xFFFFFFFFu, shi, 1);
        shi += __shfl_xor_sync(0xFFFFFFFFu, shi, 2);
        if ((lane & 3) == 0) {
            atomicAdd(&rsum[mw * 32 + mt * 16 + rquad], slo);
            atomicAdd(&rsum[mw * 32 + mt * 16 + rquad + 8], shi);
        }
    }
    __syncthreads();

#pragma unroll
    for (int mt = 0; mt < 2; mt++) {
        const int rlo = mw * 32 + mt * 16 + rquad;
        const float ilo = frcp(rsum[rlo]);
        const float ihi = frcp(rsum[rlo + 8]);
        float* olo = out + (size_t)(m0 + rlo) * KCENT;
        float* ohi = out + (size_t)(m0 + rlo + 8) * KCENT;
#pragma unroll
        for (int nt = 0; nt < 16; nt++) {
            const int col = nw * 128 + nt * 8 + cpair;
            float2 vlo = make_float2(acc[mt][nt][0] * ilo, acc[mt][nt][1] * ilo);
            float2 vhi = make_float2(acc[mt][nt][2] * ihi, acc[mt][nt][3] * ihi);
            *reinterpret_cast<float2*>(olo + col) = vlo;
            *reinterpret_cast<float2*>(ohi + col) = vhi;
        }
    }
}

// ------------------------------------------------------------------
extern "C" void kernel_launch(void* const* d_in, const int* in_sizes, int n_in,
                              void* d_out, int out_size) {
    (void)in_sizes; (void)n_in; (void)out_size;
    const float* x = (const float*)d_in[0];   // [65536, 512] f32
    const float* c = (const float*)d_in[1];   // [512, 512] f32
    float* out = (float*)d_out;               // [65536, 512] f32

    prep_c<<<KCENT / 8, 256>>>(c);
    prep_x<<<NPTS / 8, 256>>>(x);

    static bool attr_set = false;
    if (!attr_set) {
        cudaFuncSetAttribute(clu_main, cudaFuncAttributeMaxDynamicSharedMemorySize,
                             SMEM_TOTAL);
        attr_set = true;
    }
    clu_main<<<NPTS / 64, 256, SMEM_TOTAL>>>(out);
}

// round 4
// speedup vs baseline: 1.1212x; 1.1212x over previous
#include <cuda_runtime.h>
#include <cuda_bf16.h>
#include <cstdint>

#define NPTS  65536
#define DIMS  512
#define KCENT 512

// Device-global scratch (no allocations allowed in kernel_launch)
static __device__ __nv_bfloat16 g_cbf16[KCENT * DIMS];          // 512 KB
static __device__ float        g_csq[KCENT];                    // ||c||^2

__device__ __forceinline__ uint32_t smem_u32(const void* p) {
    uint32_t a;
    asm("{ .reg .u64 t; cvta.to.shared.u64 t, %1; cvt.u32.u64 %0, t; }"
        : "=r"(a) : "l"(p));
    return a;
}

__device__ __forceinline__ void ldsm_x4(uint32_t addr, uint32_t* r) {
    asm volatile("ldmatrix.sync.aligned.m8n8.x4.shared.b16 {%0,%1,%2,%3}, [%4];"
                 : "=r"(r[0]), "=r"(r[1]), "=r"(r[2]), "=r"(r[3]) : "r"(addr));
}

__device__ __forceinline__ void mma16816(float* d, const uint32_t* a,
                                         uint32_t b0, uint32_t b1) {
    asm volatile(
        "mma.sync.aligned.m16n8k16.row.col.f32.bf16.bf16.f32 "
        "{%0,%1,%2,%3}, {%4,%5,%6,%7}, {%8,%9}, {%0,%1,%2,%3};"
        : "+f"(d[0]), "+f"(d[1]), "+f"(d[2]), "+f"(d[3])
        : "r"(a[0]), "r"(a[1]), "r"(a[2]), "r"(a[3]), "r"(b0), "r"(b1));
}

__device__ __forceinline__ float frcp(float v) {
    float r;
    asm("rcp.approx.f32 %0, %1;" : "=f"(r) : "f"(v));
    return r;
}

// ------------------------------------------------------------------
// Prepass: centroids f32 -> bf16 + ||c||^2 (one warp per row)
// ------------------------------------------------------------------
__global__ void __launch_bounds__(256) prep_c(const float* __restrict__ c) {
    const int wid = threadIdx.x >> 5, lane = threadIdx.x & 31;
    const int row = blockIdx.x * 8 + wid;
    const float4* src = reinterpret_cast<const float4*>(c + (size_t)row * DIMS);
    uint2* dst = reinterpret_cast<uint2*>(g_cbf16 + (size_t)row * DIMS);
    float s = 0.0f;
#pragma unroll
    for (int i = 0; i < 4; i++) {
        float4 v = src[lane + i * 32];
        s = fmaf(v.x, v.x, s); s = fmaf(v.y, v.y, s);
        s = fmaf(v.z, v.z, s); s = fmaf(v.w, v.w, s);
        __nv_bfloat162 p0 = __floats2bfloat162_rn(v.x, v.y);
        __nv_bfloat162 p1 = __floats2bfloat162_rn(v.z, v.w);
        uint2 u;
        u.x = *reinterpret_cast<uint32_t*>(&p0);
        u.y = *reinterpret_cast<uint32_t*>(&p1);
        dst[lane + i * 32] = u;
    }
#pragma unroll
    for (int o = 16; o > 0; o >>= 1) s += __shfl_xor_sync(0xFFFFFFFFu, s, o);
    if (lane == 0) g_csq[row] = s;
}

// ------------------------------------------------------------------
// Main fused kernel: CTA = 64 rows x 512 centroids, K pipelined.
// A (x rows) loaded f32 from gmem, converted to bf16 in-flight;
// ||x||^2 accumulated during conversion.
// ------------------------------------------------------------------
#define SM_CSQ   0
#define SM_XSQ   2048
#define SM_RSUM  2304
#define SM_STAGE 2560
#define STAGE_SZ 46080
#define B_OFF    5120
#define ROWPITCH 80
#define SMEM_TOTAL (SM_STAGE + 3 * STAGE_SZ)   // 140800

// B tile for one stage: 512 rows x 32 bf16, via cp.async (one commit group)
__device__ __forceinline__ void issue_B(uint32_t sb, int s, int k0, int tid) {
    const uint32_t st = sb + SM_STAGE + s * STAGE_SZ;
#pragma unroll
    for (int i = 0; i < 8; i++) {
        const int idx = tid + i * 256;
        const int n = idx >> 2, c = idx & 3;
        const uint32_t dst = st + B_OFF + n * ROWPITCH + c * 16;
        const __nv_bfloat16* src = g_cbf16 + ((size_t)n * DIMS + k0 + c * 8);
        asm volatile("cp.async.cg.shared.global [%0], [%1], 16;"
                     :: "r"(dst), "l"(src) : "memory");
    }
    asm volatile("cp.async.commit_group;" ::: "memory");
}

// convert this thread's A chunk (2 x float4) and store bf16 to stage s
__device__ __forceinline__ void cvt_store_A(uint32_t sb, int s, int tid,
                                            float4 v0, float4 v1, float& pxsq) {
    pxsq = fmaf(v0.x, v0.x, pxsq); pxsq = fmaf(v0.y, v0.y, pxsq);
    pxsq = fmaf(v0.z, v0.z, pxsq); pxsq = fmaf(v0.w, v0.w, pxsq);
    pxsq = fmaf(v1.x, v1.x, pxsq); pxsq = fmaf(v1.y, v1.y, pxsq);
    pxsq = fmaf(v1.z, v1.z, pxsq); pxsq = fmaf(v1.w, v1.w, pxsq);
    __nv_bfloat162 p0 = __floats2bfloat162_rn(v0.x, v0.y);
    __nv_bfloat162 p1 = __floats2bfloat162_rn(v0.z, v0.w);
    __nv_bfloat162 p2 = __floats2bfloat162_rn(v1.x, v1.y);
    __nv_bfloat162 p3 = __floats2bfloat162_rn(v1.z, v1.w);
    const int r = tid >> 2, c = tid & 3;
    const uint32_t dst = sb + SM_STAGE + s * STAGE_SZ + r * ROWPITCH + c * 16;
    asm volatile("st.shared.v4.b32 [%0], {%1,%2,%3,%4};"
                 :: "r"(dst),
                    "r"(*reinterpret_cast<uint32_t*>(&p0)),
                    "r"(*reinterpret_cast<uint32_t*>(&p1)),
                    "r"(*reinterpret_cast<uint32_t*>(&p2)),
                    "r"(*reinterpret_cast<uint32_t*>(&p3)) : "memory");
}

__global__ void __launch_bounds__(256, 1)
clu_main(const float* __restrict__ x, float* __restrict__ out) {
    extern __shared__ char smem[];
    const uint32_t sb = smem_u32(smem);
    const int tid = threadIdx.x;
    const int lane = tid & 31;
    const int wid = tid >> 5;
    const int mw = wid & 1;       // 0..1
    const int nw = wid >> 1;      // 0..3
    const int m0 = blockIdx.x * 64;

    float* csq = reinterpret_cast<float*>(smem + SM_CSQ);
    float* xsq = reinterpret_cast<float*>(smem + SM_XSQ);
    float* rsum = reinterpret_cast<float*>(smem + SM_RSUM);

    csq[tid] = g_csq[tid];
    csq[tid + 256] = g_csq[tid + 256];
    if (tid < 64) {
        xsq[tid] = 1.0f;        // becomes 1 + ||x||^2 via atomicAdd
        rsum[tid] = 0.0f;
    }

    // this thread's A source: row m0 + (tid>>2), chunk (tid&3)*8 within each ktile
    const float* arow = x + (size_t)(m0 + (tid >> 2)) * DIMS + (tid & 3) * 8;
    float pxsq = 0.0f;

    // ---- prologue: fill stages 0..2 (A f32->bf16 + B cp.async) ----
    {
        float4 a0[3], a1[3];
#pragma unroll
        for (int s = 0; s < 3; s++) {
            const float4* src = reinterpret_cast<const float4*>(arow + s * 32);
            a0[s] = src[0]; a1[s] = src[1];
        }
#pragma unroll
        for (int s = 0; s < 3; s++) {
            cvt_store_A(sb, s, tid, a0[s], a1[s], pxsq);
            issue_B(sb, s, s * 32, tid);
        }
    }

    float acc[2][16][4];
#pragma unroll
    for (int mt = 0; mt < 2; mt++)
#pragma unroll
        for (int nt = 0; nt < 16; nt++)
#pragma unroll
            for (int c = 0; c < 4; c++) acc[mt][nt][c] = 0.0f;

    // ldmatrix lane address components
    const int g = lane >> 3;
    const int row_off = (lane & 7) + (g & 1) * 8;
    const int kb = (g >> 1) * 16;

#pragma unroll 1
    for (int it = 0; it < 16; ++it) {
        if (it < 14)       asm volatile("cp.async.wait_group 2;" ::: "memory");
        else if (it == 14) asm volatile("cp.async.wait_group 1;" ::: "memory");
        else               asm volatile("cp.async.wait_group 0;" ::: "memory");
        __syncthreads();

        // prefetch next A chunk (f32) — latency hidden under this tile's MMAs
        float4 pa0, pa1;
        const bool pf = (it + 3) < 16;
        if (pf) {
            const float4* src = reinterpret_cast<const float4*>(arow + (it + 3) * 32);
            pa0 = src[0]; pa1 = src[1];
        }

        const uint32_t st = sb + SM_STAGE + (it % 3) * STAGE_SZ;
        const uint32_t a_row = st + (mw * 32 + row_off) * ROWPITCH + kb;
        const uint32_t b_row = st + B_OFF + (nw * 128 + row_off) * ROWPITCH + kb;

#pragma unroll
        for (int ks = 0; ks < 2; ks++) {
            uint32_t a[2][4];
#pragma unroll
            for (int mt = 0; mt < 2; mt++)
                ldsm_x4(a_row + mt * 16 * ROWPITCH + ks * 32, a[mt]);
            uint32_t b[8][4];
#pragma unroll
            for (int p = 0; p < 8; p++)
                ldsm_x4(b_row + p * 16 * ROWPITCH + ks * 32, b[p]);
            // ldmatrix.x4 tiles: r0=n[0:8)k[0:8), r1=n[8:16)k[0:8),
            //                    r2=n[0:8)k[8:16), r3=n[8:16)k[8:16)
#pragma unroll
            for (int mt = 0; mt < 2; mt++)
#pragma unroll
                for (int p = 0; p < 8; p++) {
                    mma16816(acc[mt][2 * p],     a[mt], b[p][0], b[p][2]);
                    mma16816(acc[mt][2 * p + 1], a[mt], b[p][1], b[p][3]);
                }
        }
        __syncthreads();
        if (pf) {
            cvt_store_A(sb, it % 3, tid, pa0, pa1, pxsq);
            issue_B(sb, it % 3, (it + 3) * 32, tid);
        }
    }

    // finish ||x||^2: 4 partial sums per row
    atomicAdd(&xsq[tid >> 2], pxsq);
    __syncthreads();

    // ---- Epilogue: q = rcp(1 + ||x||^2 + ||c||^2 - 2 acc); rowsum; norm ----
    const int rquad = lane >> 2;
    const int cpair = (lane & 3) * 2;

#pragma unroll
    for (int mt = 0; mt < 2; mt++) {
        const float xlo = xsq[mw * 32 + mt * 16 + rquad];
        const float xhi = xsq[mw * 32 + mt * 16 + rquad + 8];
        float slo = 0.0f, shi = 0.0f;
#pragma unroll
        for (int nt = 0; nt < 16; nt++) {
            const int col = nw * 128 + nt * 8 + cpair;
            const float c0 = csq[col], c1 = csq[col + 1];
            float q0 = frcp(fmaf(-2.0f, acc[mt][nt][0], xlo + c0));
            float q1 = frcp(fmaf(-2.0f, acc[mt][nt][1], xlo + c1));
            float q2 = frcp(fmaf(-2.0f, acc[mt][nt][2], xhi + c0));
            float q3 = frcp(fmaf(-2.0f, acc[mt][nt][3], xhi + c1));
            acc[mt][nt][0] = q0; acc[mt][nt][1] = q1;
            acc[mt][nt][2] = q2; acc[mt][nt][3] = q3;
            slo += q0 + q1; shi += q2 + q3;
        }
        slo += __shfl_xor_sync(0xFFFFFFFFu, slo, 1);
        slo += __shfl_xor_sync(0xFFFFFFFFu, slo, 2);
        shi += __shfl_xor_sync(0xFFFFFFFFu, shi, 1);
        shi += __shfl_xor_sync(0xFFFFFFFFu, shi, 2);
        if ((lane & 3) == 0) {
            atomicAdd(&rsum[mw * 32 + mt * 16 + rquad], slo);
            atomicAdd(&rsum[mw * 32 + mt * 16 + rquad + 8], shi);
        }
    }
    __syncthreads();

#pragma unroll
    for (int mt = 0; mt < 2; mt++) {
        const int rlo = mw * 32 + mt * 16 + rquad;
        const float ilo = frcp(rsum[rlo]);
        const float ihi = frcp(rsum[rlo + 8]);
        float* olo = out + (size_t)(m0 + rlo) * KCENT;
        float* ohi = out + (size_t)(m0 + rlo + 8) * KCENT;
#pragma unroll
        for (int nt = 0; nt < 16; nt++) {
            const int col = nw * 128 + nt * 8 + cpair;
            float2 vlo = make_float2(acc[mt][nt][0] * ilo, acc[mt][nt][1] * ilo);
            float2 vhi = make_float2(acc[mt][nt][2] * ihi, acc[mt][nt][3] * ihi);
            *reinterpret_cast<float2*>(olo + col) = vlo;
            *reinterpret_cast<float2*>(ohi + col) = vhi;
        }
    }
}

// ------------------------------------------------------------------
extern "C" void kernel_launch(void* const* d_in, const int* in_sizes, int n_in,
                              void* d_out, int out_size) {
    (void)in_sizes; (void)n_in; (void)out_size;
    const float* x = (const float*)d_in[0];   // [65536, 512] f32
    const float* c = (const float*)d_in[1];   // [512, 512] f32
    float* out = (float*)d_out;               // [65536, 512] f32

    prep_c<<<KCENT / 8, 256>>>(c);

    static bool attr_set = false;
    if (!attr_set) {
        cudaFuncSetAttribute(clu_main, cudaFuncAttributeMaxDynamicSharedMemorySize,
                             SMEM_TOTAL);
        attr_set = true;
    }
    clu_main<<<NPTS / 64, 256, SMEM_TOTAL>>>(x, out);
}

// round 5
// speedup vs baseline: 1.1461x; 1.0222x over previous
#include <cuda_runtime.h>
#include <cuda_bf16.h>
#include <cstdint>

#define NPTS  65536
#define DIMS  512
#define KCENT 512

static __device__ __nv_bfloat16 g_cbf16[KCENT * DIMS];          // 512 KB
static __device__ float        g_csq[KCENT];                    // ||c||^2

__device__ __forceinline__ uint32_t smem_u32(const void* p) {
    uint32_t a;
    asm("{ .reg .u64 t; cvta.to.shared.u64 t, %1; cvt.u32.u64 %0, t; }"
        : "=r"(a) : "l"(p));
    return a;
}

__device__ __forceinline__ void ldsm_x4(uint32_t addr, uint32_t* r) {
    asm volatile("ldmatrix.sync.aligned.m8n8.x4.shared.b16 {%0,%1,%2,%3}, [%4];"
                 : "=r"(r[0]), "=r"(r[1]), "=r"(r[2]), "=r"(r[3]) : "r"(addr));
}

__device__ __forceinline__ void mma16816(float* d, const uint32_t* a,
                                         uint32_t b0, uint32_t b1) {
    asm volatile(
        "mma.sync.aligned.m16n8k16.row.col.f32.bf16.bf16.f32 "
        "{%0,%1,%2,%3}, {%4,%5,%6,%7}, {%8,%9}, {%0,%1,%2,%3};"
        : "+f"(d[0]), "+f"(d[1]), "+f"(d[2]), "+f"(d[3])
        : "r"(a[0]), "r"(a[1]), "r"(a[2]), "r"(a[3]), "r"(b0), "r"(b1));
}

__device__ __forceinline__ float frcp(float v) {
    float r;
    asm("rcp.approx.f32 %0, %1;" : "=f"(r) : "f"(v));
    return r;
}

// ------------------------------------------------------------------
// Prepass: centroids f32 -> bf16 + ||c||^2 (one warp per row)
// ------------------------------------------------------------------
__global__ void __launch_bounds__(256) prep_c(const float* __restrict__ c) {
    const int wid = threadIdx.x >> 5, lane = threadIdx.x & 31;
    const int row = blockIdx.x * 8 + wid;
    const float4* src = reinterpret_cast<const float4*>(c + (size_t)row * DIMS);
    uint2* dst = reinterpret_cast<uint2*>(g_cbf16 + (size_t)row * DIMS);
    float s = 0.0f;
#pragma unroll
    for (int i = 0; i < 4; i++) {
        float4 v = src[lane + i * 32];
        s = fmaf(v.x, v.x, s); s = fmaf(v.y, v.y, s);
        s = fmaf(v.z, v.z, s); s = fmaf(v.w, v.w, s);
        __nv_bfloat162 p0 = __floats2bfloat162_rn(v.x, v.y);
        __nv_bfloat162 p1 = __floats2bfloat162_rn(v.z, v.w);
        uint2 u;
        u.x = *reinterpret_cast<uint32_t*>(&p0);
        u.y = *reinterpret_cast<uint32_t*>(&p1);
        dst[lane + i * 32] = u;
    }
#pragma unroll
    for (int o = 16; o > 0; o >>= 1) s += __shfl_xor_sync(0xFFFFFFFFu, s, o);
    if (lane == 0) g_csq[row] = s;
}

// ------------------------------------------------------------------
// Main fused kernel: CTA = 64 rows x 512 centroids, 512 threads (16 warps),
// warp grid 2(M) x 8(N): warp tile 32 x 64. 3-stage cp.async pipeline.
// ------------------------------------------------------------------
#define SM_CSQ   0
#define SM_XSQ   2048
#define SM_RSUM  2304
#define SM_STAGE 2560
#define STAGE_SZ 46080
#define B_OFF    5120
#define ROWPITCH 80
#define SMEM_TOTAL (SM_STAGE + 3 * STAGE_SZ)   // 140800

__global__ void __launch_bounds__(512, 1)
clu_main(const float* __restrict__ x, float* __restrict__ out) {
    extern __shared__ char smem[];
    const uint32_t sb = smem_u32(smem);
    const int tid = threadIdx.x;
    const int lane = tid & 31;
    const int wid = tid >> 5;
    const int mw = wid & 1;       // 0..1  (32 rows each)
    const int nw = wid >> 1;      // 0..7  (64 cols each)
    const int m0 = blockIdx.x * 64;

    float* csq = reinterpret_cast<float*>(smem + SM_CSQ);
    float* xsq = reinterpret_cast<float*>(smem + SM_XSQ);
    float* rsum = reinterpret_cast<float*>(smem + SM_RSUM);

    csq[tid] = g_csq[tid & 511];
    if (tid < 64) {
        xsq[tid] = 1.0f;        // becomes 1 + ||x||^2 via atomicAdd
        rsum[tid] = 0.0f;
    }

    // ---- precomputed B copy descriptors: 2048 chunks / 512 thr = 4 each ----
    const __nv_bfloat16* bsrc[4];
    uint32_t bdoff[4];
#pragma unroll
    for (int i = 0; i < 4; i++) {
        const int idx = tid + i * 512;
        const int n = idx >> 2, c = idx & 3;
        bsrc[i] = g_cbf16 + (size_t)n * DIMS + c * 8;
        bdoff[i] = B_OFF + n * ROWPITCH + c * 16;
    }

    // ---- A copy: 256 chunks, threads 0..255 ----
    const bool a_owner = tid < 256;
    const float* arow = x + (size_t)(m0 + (tid >> 2)) * DIMS + (tid & 3) * 8;
    const uint32_t adoff = (tid >> 2) * ROWPITCH + (tid & 3) * 16;
    float pxsq = 0.0f;

    // ---- prologue: stages 0..2 ----
#pragma unroll
    for (int s = 0; s < 3; s++) {
        const uint32_t st = sb + SM_STAGE + s * STAGE_SZ;
        if (a_owner) {
            const float4* src = reinterpret_cast<const float4*>(arow + s * 32);
            float4 v0 = src[0], v1 = src[1];
            pxsq = fmaf(v0.x, v0.x, pxsq); pxsq = fmaf(v0.y, v0.y, pxsq);
            pxsq = fmaf(v0.z, v0.z, pxsq); pxsq = fmaf(v0.w, v0.w, pxsq);
            pxsq = fmaf(v1.x, v1.x, pxsq); pxsq = fmaf(v1.y, v1.y, pxsq);
            pxsq = fmaf(v1.z, v1.z, pxsq); pxsq = fmaf(v1.w, v1.w, pxsq);
            __nv_bfloat162 p0 = __floats2bfloat162_rn(v0.x, v0.y);
            __nv_bfloat162 p1 = __floats2bfloat162_rn(v0.z, v0.w);
            __nv_bfloat162 p2 = __floats2bfloat162_rn(v1.x, v1.y);
            __nv_bfloat162 p3 = __floats2bfloat162_rn(v1.z, v1.w);
            asm volatile("st.shared.v4.b32 [%0], {%1,%2,%3,%4};"
                         :: "r"(st + adoff),
                            "r"(*reinterpret_cast<uint32_t*>(&p0)),
                            "r"(*reinterpret_cast<uint32_t*>(&p1)),
                            "r"(*reinterpret_cast<uint32_t*>(&p2)),
                            "r"(*reinterpret_cast<uint32_t*>(&p3)) : "memory");
        }
#pragma unroll
        for (int i = 0; i < 4; i++) {
            asm volatile("cp.async.cg.shared.global [%0], [%1], 16;"
                         :: "r"(st + bdoff[i]), "l"(bsrc[i] + s * 32) : "memory");
        }
        asm volatile("cp.async.commit_group;" ::: "memory");
    }

    float acc[2][8][4];
#pragma unroll
    for (int mt = 0; mt < 2; mt++)
#pragma unroll
        for (int nt = 0; nt < 8; nt++)
#pragma unroll
            for (int c = 0; c < 4; c++) acc[mt][nt][c] = 0.0f;

    // ldmatrix lane address components
    const int g = lane >> 3;
    const int row_off = (lane & 7) + (g & 1) * 8;
    const int kb = (g >> 1) * 16;
    const uint32_t a_base = (mw * 32 + row_off) * ROWPITCH + kb;
    const uint32_t b_base = B_OFF + (nw * 64 + row_off) * ROWPITCH + kb;

#pragma unroll 1
    for (int it = 0; it < 16; ++it) {
        if (it < 14)       asm volatile("cp.async.wait_group 2;" ::: "memory");
        else if (it == 14) asm volatile("cp.async.wait_group 1;" ::: "memory");
        else               asm volatile("cp.async.wait_group 0;" ::: "memory");
        __syncthreads();

        // prefetch next A chunk (f32) — latency hidden under this tile's MMAs
        float4 pa0, pa1;
        const bool pf = (it + 3) < 16;
        if (pf && a_owner) {
            const float4* src = reinterpret_cast<const float4*>(arow + (it + 3) * 32);
            pa0 = src[0]; pa1 = src[1];
        }

        const uint32_t st = sb + SM_STAGE + (it % 3) * STAGE_SZ;
        const uint32_t a_row = st + a_base;
        const uint32_t b_row = st + b_base;

#pragma unroll
        for (int ks = 0; ks < 2; ks++) {
            uint32_t a[2][4];
#pragma unroll
            for (int mt = 0; mt < 2; mt++)
                ldsm_x4(a_row + mt * 16 * ROWPITCH + ks * 32, a[mt]);
#pragma unroll
            for (int p = 0; p < 4; p++) {
                uint32_t b[4];
                ldsm_x4(b_row + p * 16 * ROWPITCH + ks * 32, b);
                // tiles: b0=n[0:8)k[0:8), b1=n[8:16)k[0:8),
                //        b2=n[0:8)k[8:16), b3=n[8:16)k[8:16)
#pragma unroll
                for (int mt = 0; mt < 2; mt++) {
                    mma16816(acc[mt][2 * p],     a[mt], b[0], b[2]);
                    mma16816(acc[mt][2 * p + 1], a[mt], b[1], b[3]);
                }
            }
        }
        __syncthreads();
        if (pf) {
            if (a_owner) {
                pxsq = fmaf(pa0.x, pa0.x, pxsq); pxsq = fmaf(pa0.y, pa0.y, pxsq);
                pxsq = fmaf(pa0.z, pa0.z, pxsq); pxsq = fmaf(pa0.w, pa0.w, pxsq);
                pxsq = fmaf(pa1.x, pa1.x, pxsq); pxsq = fmaf(pa1.y, pa1.y, pxsq);
                pxsq = fmaf(pa1.z, pa1.z, pxsq); pxsq = fmaf(pa1.w, pa1.w, pxsq);
                __nv_bfloat162 p0 = __floats2bfloat162_rn(pa0.x, pa0.y);
                __nv_bfloat162 p1 = __floats2bfloat162_rn(pa0.z, pa0.w);
                __nv_bfloat162 p2 = __floats2bfloat162_rn(pa1.x, pa1.y);
                __nv_bfloat162 p3 = __floats2bfloat162_rn(pa1.z, pa1.w);
                asm volatile("st.shared.v4.b32 [%0], {%1,%2,%3,%4};"
                             :: "r"(st + adoff),
                                "r"(*reinterpret_cast<uint32_t*>(&p0)),
                                "r"(*reinterpret_cast<uint32_t*>(&p1)),
                                "r"(*reinterpret_cast<uint32_t*>(&p2)),
                                "r"(*reinterpret_cast<uint32_t*>(&p3)) : "memory");
            }
#pragma unroll
            for (int i = 0; i < 4; i++) {
                asm volatile("cp.async.cg.shared.global [%0], [%1], 16;"
                             :: "r"(st + bdoff[i]), "l"(bsrc[i] + (it + 3) * 32) : "memory");
            }
            asm volatile("cp.async.commit_group;" ::: "memory");
        }
    }

    // finish ||x||^2: 4 partial sums per row (threads 0..255)
    if (a_owner) atomicAdd(&xsq[tid >> 2], pxsq);
    __syncthreads();

    // ---- Epilogue: q = rcp(1 + ||x||^2 + ||c||^2 - 2 acc); rowsum; norm ----
    const int rquad = lane >> 2;
    const int cpair = (lane & 3) * 2;

#pragma unroll
    for (int mt = 0; mt < 2; mt++) {
        const float xlo = xsq[mw * 32 + mt * 16 + rquad];
        const float xhi = xsq[mw * 32 + mt * 16 + rquad + 8];
        float slo = 0.0f, shi = 0.0f;
#pragma unroll
        for (int nt = 0; nt < 8; nt++) {
            const int col = nw * 64 + nt * 8 + cpair;
            const float c0 = csq[col], c1 = csq[col + 1];
            float q0 = frcp(fmaf(-2.0f, acc[mt][nt][0], xlo + c0));
            float q1 = frcp(fmaf(-2.0f, acc[mt][nt][1], xlo + c1));
            float q2 = frcp(fmaf(-2.0f, acc[mt][nt][2], xhi + c0));
            float q3 = frcp(fmaf(-2.0f, acc[mt][nt][3], xhi + c1));
            acc[mt][nt][0] = q0; acc[mt][nt][1] = q1;
            acc[mt][nt][2] = q2; acc[mt][nt][3] = q3;
            slo += q0 + q1; shi += q2 + q3;
        }
        slo += __shfl_xor_sync(0xFFFFFFFFu, slo, 1);
        slo += __shfl_xor_sync(0xFFFFFFFFu, slo, 2);
        shi += __shfl_xor_sync(0xFFFFFFFFu, shi, 1);
        shi += __shfl_xor_sync(0xFFFFFFFFu, shi, 2);
        if ((lane & 3) == 0) {
            atomicAdd(&rsum[mw * 32 + mt * 16 + rquad], slo);
            atomicAdd(&rsum[mw * 32 + mt * 16 + rquad + 8], shi);
        }
    }
    __syncthreads();

#pragma unroll
    for (int mt = 0; mt < 2; mt++) {
        const int rlo = mw * 32 + mt * 16 + rquad;
        const float ilo = frcp(rsum[rlo]);
        const float ihi = frcp(rsum[rlo + 8]);
        float* olo = out + (size_t)(m0 + rlo) * KCENT;
        float* ohi = out + (size_t)(m0 + rlo + 8) * KCENT;
#pragma unroll
        for (int nt = 0; nt < 8; nt++) {
            const int col = nw * 64 + nt * 8 + cpair;
            float2 vlo = make_float2(acc[mt][nt][0] * ilo, acc[mt][nt][1] * ilo);
            float2 vhi = make_float2(acc[mt][nt][2] * ihi, acc[mt][nt][3] * ihi);
            *reinterpret_cast<float2*>(olo + col) = vlo;
            *reinterpret_cast<float2*>(ohi + col) = vhi;
        }
    }
}

// ------------------------------------------------------------------
extern "C" void kernel_launch(void* const* d_in, const int* in_sizes, int n_in,
                              void* d_out, int out_size) {
    (void)in_sizes; (void)n_in; (void)out_size;
    const float* x = (const float*)d_in[0];   // [65536, 512] f32
    const float* c = (const float*)d_in[1];   // [512, 512] f32
    float* out = (float*)d_out;               // [65536, 512] f32

    prep_c<<<KCENT / 8, 256>>>(c);

    static bool attr_set = false;
    if (!attr_set) {
        cudaFuncSetAttribute(clu_main, cudaFuncAttributeMaxDynamicSharedMemorySize,
                             SMEM_TOTAL);
        attr_set = true;
    }
    clu_main<<<NPTS / 64, 512, SMEM_TOTAL>>>(x, out);
}

// round 6
// speedup vs baseline: 1.1702x; 1.0211x over previous
#include <cuda_runtime.h>
#include <cuda_bf16.h>
#include <cstdint>

#define NPTS  65536
#define DIMS  512
#define KCENT 512

static __device__ __nv_bfloat16 g_cbf16[KCENT * DIMS];          // 512 KB
static __device__ float        g_csq[KCENT];                    // ||c||^2

__device__ __forceinline__ uint32_t smem_u32(const void* p) {
    uint32_t a;
    asm("{ .reg .u64 t; cvta.to.shared.u64 t, %1; cvt.u32.u64 %0, t; }"
        : "=r"(a) : "l"(p));
    return a;
}

__device__ __forceinline__ void ldsm_x4(uint32_t addr, uint32_t* r) {
    asm volatile("ldmatrix.sync.aligned.m8n8.x4.shared.b16 {%0,%1,%2,%3}, [%4];"
                 : "=r"(r[0]), "=r"(r[1]), "=r"(r[2]), "=r"(r[3]) : "r"(addr));
}

__device__ __forceinline__ void mma16816(float* d, const uint32_t* a,
                                         uint32_t b0, uint32_t b1) {
    asm volatile(
        "mma.sync.aligned.m16n8k16.row.col.f32.bf16.bf16.f32 "
        "{%0,%1,%2,%3}, {%4,%5,%6,%7}, {%8,%9}, {%0,%1,%2,%3};"
        : "+f"(d[0]), "+f"(d[1]), "+f"(d[2]), "+f"(d[3])
        : "r"(a[0]), "r"(a[1]), "r"(a[2]), "r"(a[3]), "r"(b0), "r"(b1));
}

__device__ __forceinline__ float frcp(float v) {
    float r;
    asm("rcp.approx.f32 %0, %1;" : "=f"(r) : "f"(v));
    return r;
}

// ------------------------------------------------------------------
// Prepass: centroids f32 -> bf16 + ||c||^2 (one warp per row)
// ------------------------------------------------------------------
__global__ void __launch_bounds__(256) prep_c(const float* __restrict__ c) {
    const int wid = threadIdx.x >> 5, lane = threadIdx.x & 31;
    const int row = blockIdx.x * 8 + wid;
    const float4* src = reinterpret_cast<const float4*>(c + (size_t)row * DIMS);
    uint2* dst = reinterpret_cast<uint2*>(g_cbf16 + (size_t)row * DIMS);
    float s = 0.0f;
#pragma unroll
    for (int i = 0; i < 4; i++) {
        float4 v = src[lane + i * 32];
        s = fmaf(v.x, v.x, s); s = fmaf(v.y, v.y, s);
        s = fmaf(v.z, v.z, s); s = fmaf(v.w, v.w, s);
        __nv_bfloat162 p0 = __floats2bfloat162_rn(v.x, v.y);
        __nv_bfloat162 p1 = __floats2bfloat162_rn(v.z, v.w);
        uint2 u;
        u.x = *reinterpret_cast<uint32_t*>(&p0);
        u.y = *reinterpret_cast<uint32_t*>(&p1);
        dst[lane + i * 32] = u;
    }
#pragma unroll
    for (int o = 16; o > 0; o >>= 1) s += __shfl_xor_sync(0xFFFFFFFFu, s, o);
    if (lane == 0) g_csq[row] = s;
}

// ------------------------------------------------------------------
// Main fused kernel: CTA = 64 rows x 512 cols, 512 threads (16 warps),
// warp tile 32x64. ONE __syncthreads per K-iteration.
// B: 3-stage cp.async ring. A: 4-slot bf16 ring, LDG f32 prefetch +3,
// STS +2, readers always >= 2 barriers behind the writer.
// ------------------------------------------------------------------
#define SM_CSQ   0
#define SM_XSQ   2048
#define SM_RSUM  2304
#define SM_ARING 2560             // 4 slots x (64 rows x 80B) = 20480
#define A_SLOT   5120
#define SM_BRING 23040            // 3 stages x (512 rows x 80B) = 122880
#define B_STAGE  40960
#define ROWPITCH 80
#define SMEM_TOTAL (SM_BRING + 3 * B_STAGE)   // 145920

__global__ void __launch_bounds__(512, 1)
clu_main(const float* __restrict__ x, float* __restrict__ out) {
    extern __shared__ char smem[];
    const uint32_t sb = smem_u32(smem);
    const int tid = threadIdx.x;
    const int lane = tid & 31;
    const int wid = tid >> 5;
    const int mw = wid & 1;       // 0..1  (32 rows each)
    const int nw = wid >> 1;      // 0..7  (64 cols each)
    const int m0 = blockIdx.x * 64;

    float* csq = reinterpret_cast<float*>(smem + SM_CSQ);
    float* xsq = reinterpret_cast<float*>(smem + SM_XSQ);
    float* rsum = reinterpret_cast<float*>(smem + SM_RSUM);

    csq[tid] = g_csq[tid & 511];
    if (tid < 64) {
        xsq[tid] = 1.0f;        // becomes 1 + ||x||^2 via atomicAdd
        rsum[tid] = 0.0f;
    }

    // ---- B copy descriptors: 2048 16B-chunks / 512 thr = 4 each ----
    const __nv_bfloat16* bsrc[4];
    uint32_t bdoff[4];
#pragma unroll
    for (int i = 0; i < 4; i++) {
        const int idx = tid + i * 512;
        const int n = idx >> 2, c = idx & 3;
        bsrc[i] = g_cbf16 + (size_t)n * DIMS + c * 8;
        bdoff[i] = SM_BRING + n * ROWPITCH + c * 16;
    }

    // ---- A copy: threads 0..255, one 8-float chunk each per K-tile ----
    const bool a_owner = tid < 256;
    const float* arow = x + (size_t)(m0 + (tid >> 2)) * DIMS + (tid & 3) * 8;
    const uint32_t adoff = SM_ARING + (tid >> 2) * ROWPITCH + (tid & 3) * 16;
    float pxsq = 0.0f;

    // held A prefetch (8 floats) for chunk "it+3" at iteration it
    float4 ha0, ha1;

    // cvt+STS helper inline: stores held floats to slot, accumulates ||x||^2
#define CVT_STS_A(slot, v0, v1) do {                                          \
        pxsq = fmaf((v0).x, (v0).x, pxsq); pxsq = fmaf((v0).y, (v0).y, pxsq); \
        pxsq = fmaf((v0).z, (v0).z, pxsq); pxsq = fmaf((v0).w, (v0).w, pxsq); \
        pxsq = fmaf((v1).x, (v1).x, pxsq); pxsq = fmaf((v1).y, (v1).y, pxsq); \
        pxsq = fmaf((v1).z, (v1).z, pxsq); pxsq = fmaf((v1).w, (v1).w, pxsq); \
        __nv_bfloat162 p0 = __floats2bfloat162_rn((v0).x, (v0).y);            \
        __nv_bfloat162 p1 = __floats2bfloat162_rn((v0).z, (v0).w);            \
        __nv_bfloat162 p2 = __floats2bfloat162_rn((v1).x, (v1).y);            \
        __nv_bfloat162 p3 = __floats2bfloat162_rn((v1).z, (v1).w);            \
        asm volatile("st.shared.v4.b32 [%0], {%1,%2,%3,%4};"                  \
                     :: "r"(sb + adoff + (slot) * A_SLOT),                    \
                        "r"(*reinterpret_cast<uint32_t*>(&p0)),               \
                        "r"(*reinterpret_cast<uint32_t*>(&p1)),               \
                        "r"(*reinterpret_cast<uint32_t*>(&p2)),               \
                        "r"(*reinterpret_cast<uint32_t*>(&p3)) : "memory");   \
    } while (0)

#define ISSUE_B(stage, k0) do {                                               \
        const uint32_t _st = sb + (stage) * B_STAGE;                          \
        _Pragma("unroll")                                                     \
        for (int i = 0; i < 4; i++) {                                         \
            asm volatile("cp.async.cg.shared.global [%0], [%1], 16;"          \
                         :: "r"(_st + bdoff[i]), "l"(bsrc[i] + (k0) * 32)     \
                         : "memory");                                         \
        }                                                                     \
        asm volatile("cp.async.commit_group;" ::: "memory");                  \
    } while (0)

    // ---- prologue: A slots 0,1 + held chunk 2; B groups 0,1 ----
    if (a_owner) {
        const float4* s0 = reinterpret_cast<const float4*>(arow);
        const float4* s1 = reinterpret_cast<const float4*>(arow + 32);
        const float4* s2 = reinterpret_cast<const float4*>(arow + 64);
        float4 a00 = s0[0], a01 = s0[1];
        float4 a10 = s1[0], a11 = s1[1];
        ha0 = s2[0]; ha1 = s2[1];
        CVT_STS_A(0, a00, a01);
        CVT_STS_A(1, a10, a11);
    }
    ISSUE_B(0, 0);
    ISSUE_B(1, 1);

    float acc[2][8][4];
#pragma unroll
    for (int mt = 0; mt < 2; mt++)
#pragma unroll
        for (int nt = 0; nt < 8; nt++)
#pragma unroll
            for (int c = 0; c < 4; c++) acc[mt][nt][c] = 0.0f;

    // ldmatrix lane address components
    const int g = lane >> 3;
    const int row_off = (lane & 7) + (g & 1) * 8;
    const int kb = (g >> 1) * 16;
    const uint32_t a_base = SM_ARING + (mw * 32 + row_off) * ROWPITCH + kb;
    const uint32_t b_base = SM_BRING + (nw * 64 + row_off) * ROWPITCH + kb;

#pragma unroll 1
    for (int it = 0; it < 16; ++it) {
        if (it < 14) asm volatile("cp.async.wait_group 1;" ::: "memory");
        else         asm volatile("cp.async.wait_group 0;" ::: "memory");
        __syncthreads();   // the ONLY barrier this iteration

        // stage (it+2)%3 and A slot (it+2)&3 are free (readers were at it-1 / it-2)
        if (it + 2 < 16) {
            ISSUE_B((it + 2) % 3, it + 2);
            if (a_owner) {
                CVT_STS_A((it + 2) & 3, ha0, ha1);
                if (it + 3 < 16) {
                    const float4* src =
                        reinterpret_cast<const float4*>(arow + (it + 3) * 32);
                    ha0 = src[0]; ha1 = src[1];
                }
            }
        }

        const uint32_t a_row = sb + a_base + (it & 3) * A_SLOT;
        const uint32_t b_row = sb + b_base + (it % 3) * B_STAGE;

#pragma unroll
        for (int ks = 0; ks < 2; ks++) {
            uint32_t a[2][4];
#pragma unroll
            for (int mt = 0; mt < 2; mt++)
                ldsm_x4(a_row + mt * 16 * ROWPITCH + ks * 32, a[mt]);
#pragma unroll
            for (int p = 0; p < 4; p++) {
                uint32_t b[4];
                ldsm_x4(b_row + p * 16 * ROWPITCH + ks * 32, b);
                // tiles: b0=n[0:8)k[0:8), b1=n[8:16)k[0:8),
                //        b2=n[0:8)k[8:16), b3=n[8:16)k[8:16)
#pragma unroll
                for (int mt = 0; mt < 2; mt++) {
                    mma16816(acc[mt][2 * p],     a[mt], b[0], b[2]);
                    mma16816(acc[mt][2 * p + 1], a[mt], b[1], b[3]);
                }
            }
        }
    }

    // finish ||x||^2: 4 partial sums per row (threads 0..255)
    if (a_owner) atomicAdd(&xsq[tid >> 2], pxsq);
    __syncthreads();

    // ---- Epilogue: q = rcp(1 + ||x||^2 + ||c||^2 - 2 acc); rowsum; norm ----
    const int rquad = lane >> 2;
    const int cpair = (lane & 3) * 2;

#pragma unroll
    for (int mt = 0; mt < 2; mt++) {
        const float xlo = xsq[mw * 32 + mt * 16 + rquad];
        const float xhi = xsq[mw * 32 + mt * 16 + rquad + 8];
        float slo = 0.0f, shi = 0.0f;
#pragma unroll
        for (int nt = 0; nt < 8; nt++) {
            const int col = nw * 64 + nt * 8 + cpair;
            const float c0 = csq[col], c1 = csq[col + 1];
            float q0 = frcp(fmaf(-2.0f, acc[mt][nt][0], xlo + c0));
            float q1 = frcp(fmaf(-2.0f, acc[mt][nt][1], xlo + c1));
            float q2 = frcp(fmaf(-2.0f, acc[mt][nt][2], xhi + c0));
            float q3 = frcp(fmaf(-2.0f, acc[mt][nt][3], xhi + c1));
            acc[mt][nt][0] = q0; acc[mt][nt][1] = q1;
            acc[mt][nt][2] = q2; acc[mt][nt][3] = q3;
            slo += q0 + q1; shi += q2 + q3;
        }
        slo += __shfl_xor_sync(0xFFFFFFFFu, slo, 1);
        slo += __shfl_xor_sync(0xFFFFFFFFu, slo, 2);
        shi += __shfl_xor_sync(0xFFFFFFFFu, shi, 1);
        shi += __shfl_xor_sync(0xFFFFFFFFu, shi, 2);
        if ((lane & 3) == 0) {
            atomicAdd(&rsum[mw * 32 + mt * 16 + rquad], slo);
            atomicAdd(&rsum[mw * 32 + mt * 16 + rquad + 8], shi);
        }
    }
    __syncthreads();

#pragma unroll
    for (int mt = 0; mt < 2; mt++) {
        const int rlo = mw * 32 + mt * 16 + rquad;
        const float ilo = frcp(rsum[rlo]);
        const float ihi = frcp(rsum[rlo + 8]);
        float* olo = out + (size_t)(m0 + rlo) * KCENT;
        float* ohi = out + (size_t)(m0 + rlo + 8) * KCENT;
#pragma unroll
        for (int nt = 0; nt < 8; nt++) {
            const int col = nw * 64 + nt * 8 + cpair;
            float2 vlo = make_float2(acc[mt][nt][0] * ilo, acc[mt][nt][1] * ilo);
            float2 vhi = make_float2(acc[mt][nt][2] * ihi, acc[mt][nt][3] * ihi);
            *reinterpret_cast<float2*>(olo + col) = vlo;
            *reinterpret_cast<float2*>(ohi + col) = vhi;
        }
    }
}

// ------------------------------------------------------------------
extern "C" void kernel_launch(void* const* d_in, const int* in_sizes, int n_in,
                              void* d_out, int out_size) {
    (void)in_sizes; (void)n_in; (void)out_size;
    const float* x = (const float*)d_in[0];   // [65536, 512] f32
    const float* c = (const float*)d_in[1];   // [512, 512] f32
    float* out = (float*)d_out;               // [65536, 512] f32

    prep_c<<<KCENT / 8, 256>>>(c);

    static bool attr_set = false;
    if (!attr_set) {
        cudaFuncSetAttribute(clu_main, cudaFuncAttributeMaxDynamicSharedMemorySize,
                             SMEM_TOTAL);
        attr_set = true;
    }
    clu_main<<<NPTS / 64, 512, SMEM_TOTAL>>>(x, out);
}

// round 7
// speedup vs baseline: 1.1961x; 1.0221x over previous
#include <cuda_runtime.h>
#include <cuda_bf16.h>
#include <cstdint>

#define NPTS  65536
#define DIMS  512
#define KCENT 512

static __device__ __nv_bfloat16 g_cbf16[KCENT * DIMS];          // 512 KB
static __device__ float        g_csq[KCENT];                    // ||c||^2

__device__ __forceinline__ uint32_t smem_u32(const void* p) {
    uint32_t a;
    asm("{ .reg .u64 t; cvta.to.shared.u64 t, %1; cvt.u32.u64 %0, t; }"
        : "=r"(a) : "l"(p));
    return a;
}

__device__ __forceinline__ void ldsm_x4(uint32_t addr, uint32_t* r) {
    asm volatile("ldmatrix.sync.aligned.m8n8.x4.shared.b16 {%0,%1,%2,%3}, [%4];"
                 : "=r"(r[0]), "=r"(r[1]), "=r"(r[2]), "=r"(r[3]) : "r"(addr));
}

__device__ __forceinline__ void mma16816(float* d, const uint32_t* a,
                                         uint32_t b0, uint32_t b1) {
    asm volatile(
        "mma.sync.aligned.m16n8k16.row.col.f32.bf16.bf16.f32 "
        "{%0,%1,%2,%3}, {%4,%5,%6,%7}, {%8,%9}, {%0,%1,%2,%3};"
        : "+f"(d[0]), "+f"(d[1]), "+f"(d[2]), "+f"(d[3])
        : "r"(a[0]), "r"(a[1]), "r"(a[2]), "r"(a[3]), "r"(b0), "r"(b1));
}

__device__ __forceinline__ float frcp(float v) {
    float r;
    asm("rcp.approx.f32 %0, %1;" : "=f"(r) : "f"(v));
    return r;
}

// ------------------------------------------------------------------
// Prepass: centroids f32 -> bf16 + ||c||^2 (one warp per row)
// ------------------------------------------------------------------
__global__ void __launch_bounds__(256) prep_c(const float* __restrict__ c) {
    const int wid = threadIdx.x >> 5, lane = threadIdx.x & 31;
    const int row = blockIdx.x * 8 + wid;
    const float4* src = reinterpret_cast<const float4*>(c + (size_t)row * DIMS);
    uint2* dst = reinterpret_cast<uint2*>(g_cbf16 + (size_t)row * DIMS);
    float s = 0.0f;
#pragma unroll
    for (int i = 0; i < 4; i++) {
        float4 v = src[lane + i * 32];
        s = fmaf(v.x, v.x, s); s = fmaf(v.y, v.y, s);
        s = fmaf(v.z, v.z, s); s = fmaf(v.w, v.w, s);
        __nv_bfloat162 p0 = __floats2bfloat162_rn(v.x, v.y);
        __nv_bfloat162 p1 = __floats2bfloat162_rn(v.z, v.w);
        uint2 u;
        u.x = *reinterpret_cast<uint32_t*>(&p0);
        u.y = *reinterpret_cast<uint32_t*>(&p1);
        dst[lane + i * 32] = u;
    }
#pragma unroll
    for (int o = 16; o > 0; o >>= 1) s += __shfl_xor_sync(0xFFFFFFFFu, s, o);
    if (lane == 0) g_csq[row] = s;
}

// ------------------------------------------------------------------
// Main fused kernel: CTA = 64 rows x 512 cols, 512 threads (16 warps),
// warp tile 32x64. ONE __syncthreads per K-iteration. 4-stage B ring.
// Inner k=32 tile: 4 half-steps of 8 MMAs with LDSM issued one half ahead.
// ------------------------------------------------------------------
#define SM_CSQ   0
#define SM_XSQ   2048
#define SM_RSUM  2304
#define SM_ARING 2560             // 4 slots x (64 rows x 80B) = 20480
#define A_SLOT   5120
#define SM_BRING 23040            // 4 stages x (512 rows x 80B) = 163840
#define B_STAGE  40960
#define ROWPITCH 80
#define SMEM_TOTAL (SM_BRING + 4 * B_STAGE)   // 186880

__global__ void __launch_bounds__(512, 1)
clu_main(const float* __restrict__ x, float* __restrict__ out) {
    extern __shared__ char smem[];
    const uint32_t sb = smem_u32(smem);
    const int tid = threadIdx.x;
    const int lane = tid & 31;
    const int wid = tid >> 5;
    const int mw = wid & 1;       // 0..1  (32 rows each)
    const int nw = wid >> 1;      // 0..7  (64 cols each)
    const int m0 = blockIdx.x * 64;

    float* csq = reinterpret_cast<float*>(smem + SM_CSQ);
    float* xsq = reinterpret_cast<float*>(smem + SM_XSQ);
    float* rsum = reinterpret_cast<float*>(smem + SM_RSUM);

    csq[tid] = g_csq[tid & 511];
    if (tid < 64) {
        xsq[tid] = 1.0f;        // becomes 1 + ||x||^2 via atomicAdd
        rsum[tid] = 0.0f;
    }

    // ---- B copy bases: thread handles chunks i=0..3; offsets are constants ----
    // idx = tid + i*512 ; n = (tid>>2) + i*128 ; c = tid&3 (same for all i)
    const __nv_bfloat16* bsrc0 =
        g_cbf16 + (size_t)(tid >> 2) * DIMS + (tid & 3) * 8;           // + i*65536 elems
    const uint32_t bdst0 = sb + SM_BRING + (tid >> 2) * ROWPITCH + (tid & 3) * 16; // + i*10240

#define ISSUE_B(stage, k0) do {                                               \
        const uint32_t _soff = (stage) * B_STAGE;                             \
        const int _koff = (k0) * 32;                                          \
        asm volatile("cp.async.cg.shared.global [%0], [%1], 16;"              \
            :: "r"(bdst0 + _soff), "l"(bsrc0 + _koff) : "memory");            \
        asm volatile("cp.async.cg.shared.global [%0], [%1], 16;"              \
            :: "r"(bdst0 + _soff + 10240), "l"(bsrc0 + _koff + 65536) : "memory"); \
        asm volatile("cp.async.cg.shared.global [%0], [%1], 16;"              \
            :: "r"(bdst0 + _soff + 20480), "l"(bsrc0 + _koff + 131072) : "memory"); \
        asm volatile("cp.async.cg.shared.global [%0], [%1], 16;"              \
            :: "r"(bdst0 + _soff + 30720), "l"(bsrc0 + _koff + 196608) : "memory"); \
        asm volatile("cp.async.commit_group;" ::: "memory");                  \
    } while (0)

    // ---- A copy: threads 0..255, one 8-float chunk each per K-tile ----
    const bool a_owner = tid < 256;
    const float* arow = x + (size_t)(m0 + (tid >> 2)) * DIMS + (tid & 3) * 8;
    const uint32_t adst = sb + SM_ARING + (tid >> 2) * ROWPITCH + (tid & 3) * 16;
    float pxsq = 0.0f;
    float4 ha0, ha1;   // held A prefetch for chunk "it+3"

#define CVT_STS_A(slot, v0, v1) do {                                          \
        pxsq = fmaf((v0).x, (v0).x, pxsq); pxsq = fmaf((v0).y, (v0).y, pxsq); \
        pxsq = fmaf((v0).z, (v0).z, pxsq); pxsq = fmaf((v0).w, (v0).w, pxsq); \
        pxsq = fmaf((v1).x, (v1).x, pxsq); pxsq = fmaf((v1).y, (v1).y, pxsq); \
        pxsq = fmaf((v1).z, (v1).z, pxsq); pxsq = fmaf((v1).w, (v1).w, pxsq); \
        __nv_bfloat162 p0 = __floats2bfloat162_rn((v0).x, (v0).y);            \
        __nv_bfloat162 p1 = __floats2bfloat162_rn((v0).z, (v0).w);            \
        __nv_bfloat162 p2 = __floats2bfloat162_rn((v1).x, (v1).y);            \
        __nv_bfloat162 p3 = __floats2bfloat162_rn((v1).z, (v1).w);            \
        asm volatile("st.shared.v4.b32 [%0], {%1,%2,%3,%4};"                  \
                     :: "r"(adst + (slot) * A_SLOT),                          \
                        "r"(*reinterpret_cast<uint32_t*>(&p0)),               \
                        "r"(*reinterpret_cast<uint32_t*>(&p1)),               \
                        "r"(*reinterpret_cast<uint32_t*>(&p2)),               \
                        "r"(*reinterpret_cast<uint32_t*>(&p3)) : "memory");   \
    } while (0)

    // ---- prologue: B tiles 0,1,2 ; A slots 0,1 + held chunk 2 ----
    if (a_owner) {
        const float4* s0 = reinterpret_cast<const float4*>(arow);
        const float4* s1 = reinterpret_cast<const float4*>(arow + 32);
        const float4* s2 = reinterpret_cast<const float4*>(arow + 64);
        float4 a00 = s0[0], a01 = s0[1];
        float4 a10 = s1[0], a11 = s1[1];
        ha0 = s2[0]; ha1 = s2[1];
        CVT_STS_A(0, a00, a01);
        CVT_STS_A(1, a10, a11);
    }
    ISSUE_B(0, 0);
    ISSUE_B(1, 1);
    ISSUE_B(2, 2);

    float acc[2][8][4];
#pragma unroll
    for (int mt = 0; mt < 2; mt++)
#pragma unroll
        for (int nt = 0; nt < 8; nt++)
#pragma unroll
            for (int c = 0; c < 4; c++) acc[mt][nt][c] = 0.0f;

    // ldmatrix lane address components
    const int g = lane >> 3;
    const int row_off = (lane & 7) + (g & 1) * 8;
    const int kb = (g >> 1) * 16;
    const uint32_t a_base = sb + SM_ARING + (mw * 32 + row_off) * ROWPITCH + kb;
    const uint32_t b_base = sb + SM_BRING + (nw * 64 + row_off) * ROWPITCH + kb;

    // 8 MMAs: n-tile pair {p, p+1} with one a buffer
#define MMA_HALF(abuf, bA, bB, p0i) do {                                      \
        mma16816(acc[0][2*(p0i)],     (abuf)[0], (bA)[0], (bA)[2]);           \
        mma16816(acc[0][2*(p0i)+1],   (abuf)[0], (bA)[1], (bA)[3]);           \
        mma16816(acc[1][2*(p0i)],     (abuf)[1], (bA)[0], (bA)[2]);           \
        mma16816(acc[1][2*(p0i)+1],   (abuf)[1], (bA)[1], (bA)[3]);           \
        mma16816(acc[0][2*(p0i)+2],   (abuf)[0], (bB)[0], (bB)[2]);           \
        mma16816(acc[0][2*(p0i)+3],   (abuf)[0], (bB)[1], (bB)[3]);           \
        mma16816(acc[1][2*(p0i)+2],   (abuf)[1], (bB)[0], (bB)[2]);           \
        mma16816(acc[1][2*(p0i)+3],   (abuf)[1], (bB)[1], (bB)[3]);           \
    } while (0)

#pragma unroll 1
    for (int it = 0; it < 16; ++it) {
        if (it <= 13)      asm volatile("cp.async.wait_group 2;" ::: "memory");
        else if (it == 14) asm volatile("cp.async.wait_group 1;" ::: "memory");
        else               asm volatile("cp.async.wait_group 0;" ::: "memory");
        __syncthreads();   // the ONLY barrier this iteration

        if (it + 3 < 16) ISSUE_B((it + 3) & 3, it + 3);
        if (a_owner && it + 2 < 16) {
            CVT_STS_A((it + 2) & 3, ha0, ha1);
            if (it + 3 < 16) {
                const float4* src =
                    reinterpret_cast<const float4*>(arow + (it + 3) * 32);
                ha0 = src[0]; ha1 = src[1];
            }
        }

        const uint32_t a_row = a_base + (it & 3) * A_SLOT;
        const uint32_t b_row = b_base + (it & 3) * B_STAGE;

        // ---- software-pipelined fragment schedule (4 half-steps) ----
        uint32_t aA[2][4], aB[2][4];
        uint32_t b0[4], b1[4], b2[4], b3[4], b4[4], b5[4], b6[4], b7[4];

        // preload: a(ks0) + b half0 (ks0: p0,p1)
        ldsm_x4(a_row, aA[0]);
        ldsm_x4(a_row + 16 * ROWPITCH, aA[1]);
        ldsm_x4(b_row, b0);
        ldsm_x4(b_row + 16 * ROWPITCH, b1);

        // half1 loads (ks0: p2,p3), then MMA half0
        ldsm_x4(b_row + 32 * ROWPITCH, b2);
        ldsm_x4(b_row + 48 * ROWPITCH, b3);
        MMA_HALF(aA, b0, b1, 0);

        // half2 loads (ks1: a + p0,p1), then MMA half1
        ldsm_x4(a_row + 32, aB[0]);
        ldsm_x4(a_row + 16 * ROWPITCH + 32, aB[1]);
        ldsm_x4(b_row + 32, b4);
        ldsm_x4(b_row + 16 * ROWPITCH + 32, b5);
        MMA_HALF(aA, b2, b3, 2);

        // half3 loads (ks1: p2,p3), then MMA half2
        ldsm_x4(b_row + 32 * ROWPITCH + 32, b6);
        ldsm_x4(b_row + 48 * ROWPITCH + 32, b7);
        MMA_HALF(aB, b4, b5, 0);

        // MMA half3
        MMA_HALF(aB, b6, b7, 2);
    }

    // finish ||x||^2: 4 partial sums per row (threads 0..255)
    if (a_owner) atomicAdd(&xsq[tid >> 2], pxsq);
    __syncthreads();

    // ---- Epilogue: q = rcp(1 + ||x||^2 + ||c||^2 - 2 acc); rowsum; norm ----
    const int rquad = lane >> 2;
    const int cpair = (lane & 3) * 2;

#pragma unroll
    for (int mt = 0; mt < 2; mt++) {
        const float xlo = xsq[mw * 32 + mt * 16 + rquad];
        const float xhi = xsq[mw * 32 + mt * 16 + rquad + 8];
        float slo = 0.0f, shi = 0.0f;
#pragma unroll
        for (int nt = 0; nt < 8; nt++) {
            const int col = nw * 64 + nt * 8 + cpair;
            const float c0 = csq[col], c1 = csq[col + 1];
            float q0 = frcp(fmaf(-2.0f, acc[mt][nt][0], xlo + c0));
            float q1 = frcp(fmaf(-2.0f, acc[mt][nt][1], xlo + c1));
            float q2 = frcp(fmaf(-2.0f, acc[mt][nt][2], xhi + c0));
            float q3 = frcp(fmaf(-2.0f, acc[mt][nt][3], xhi + c1));
            acc[mt][nt][0] = q0; acc[mt][nt][1] = q1;
            acc[mt][nt][2] = q2; acc[mt][nt][3] = q3;
            slo += q0 + q1; shi += q2 + q3;
        }
        slo += __shfl_xor_sync(0xFFFFFFFFu, slo, 1);
        slo += __shfl_xor_sync(0xFFFFFFFFu, slo, 2);
        shi += __shfl_xor_sync(0xFFFFFFFFu, shi, 1);
        shi += __shfl_xor_sync(0xFFFFFFFFu, shi, 2);
        if ((lane & 3) == 0) {
            atomicAdd(&rsum[mw * 32 + mt * 16 + rquad], slo);
            atomicAdd(&rsum[mw * 32 + mt * 16 + rquad + 8], shi);
        }
    }
    __syncthreads();

#pragma unroll
    for (int mt = 0; mt < 2; mt++) {
        const int rlo = mw * 32 + mt * 16 + rquad;
        const float ilo = frcp(rsum[rlo]);
        const float ihi = frcp(rsum[rlo + 8]);
        float* olo = out + (size_t)(m0 + rlo) * KCENT;
        float* ohi = out + (size_t)(m0 + rlo + 8) * KCENT;
#pragma unroll
        for (int nt = 0; nt < 8; nt++) {
            const int col = nw * 64 + nt * 8 + cpair;
            float2 vlo = make_float2(acc[mt][nt][0] * ilo, acc[mt][nt][1] * ilo);
            float2 vhi = make_float2(acc[mt][nt][2] * ihi, acc[mt][nt][3] * ihi);
            *reinterpret_cast<float2*>(olo + col) = vlo;
            *reinterpret_cast<float2*>(ohi + col) = vhi;
        }
    }
}

// ------------------------------------------------------------------
extern "C" void kernel_launch(void* const* d_in, const int* in_sizes, int n_in,
                              void* d_out, int out_size) {
    (void)in_sizes; (void)n_in; (void)out_size;
    const float* x = (const float*)d_in[0];   // [65536, 512] f32
    const float* c = (const float*)d_in[1];   // [512, 512] f32
    float* out = (float*)d_out;               // [65536, 512] f32

    prep_c<<<KCENT / 8, 256>>>(c);

    static bool attr_set = false;
    if (!attr_set) {
        cudaFuncSetAttribute(clu_main, cudaFuncAttributeMaxDynamicSharedMemorySize,
                             SMEM_TOTAL);
        attr_set = true;
    }
    clu_main<<<NPTS / 64, 512, SMEM_TOTAL>>>(x, out);
}